// round 11
// baseline (speedup 1.0000x reference)
#include <cuda_runtime.h>
#include <cstdint>

#define NTH  256
#define NHID 6

// Atom-packed layout for a 128-row x K-col tf32 operand:
//   word(row,k) = (k>>2)*512 + (row>>3)*32 + (row&7)*4 + (k&3)
// -> the 8 rows x 4 floats of one ldmatrix 8x8(b16) tile are ONE 128B line.

// float offsets in dynamic smem
#define F_ADJ  0                 // 16384: adj (A of GEMM2), rows=p, k=n
#define F_ACT  16384             // 16384: X / Y^T / X' multiplexed
#define F_WT   32768             // 16384: W^T (A of GEMM1), rows=u, k=c
#define F_X0   49152             // 2048:  x0, rows=p, k=c(16)
#define F_WINT 51200             // 2048:  W_in^T, rows=u, k=c(16)
#define F_BIN  53248             // 128
#define F_BIA  53376             // 768
#define F_MSK  54144             // 128
#define F_WO   54272             // 128
#define F_PART 54400             // 256
#define F_RED  54656             // 8 (RED[7] = denom)
#define F_BOUT 54664
#define SMEM_FLOATS 54672
#define SMEM_BYTES  (SMEM_FLOATS * 4)

__device__ __forceinline__ uint32_t smem_u32(const void* p) {
    uint32_t a;
    asm("{ .reg .u64 t; cvta.to.shared.u64 t, %1; cvt.u32.u64 %0, t; }" : "=r"(a) : "l"(p));
    return a;
}

__device__ __forceinline__ float tf32r(float x) {
    float y;
    asm("cvt.rna.tf32.f32 %0, %1;" : "=f"(y) : "f"(x));
    return y;
}

__device__ __forceinline__ void ldsm4(uint32_t addr, uint32_t& r0, uint32_t& r1,
                                      uint32_t& r2, uint32_t& r3) {
    asm volatile("ldmatrix.sync.aligned.m8n8.x4.shared.b16 {%0,%1,%2,%3}, [%4];"
                 : "=r"(r0), "=r"(r1), "=r"(r2), "=r"(r3) : "r"(addr));
}

__device__ __forceinline__ void mma8(float* d,
                                     uint32_t a0, uint32_t a1, uint32_t a2, uint32_t a3,
                                     uint32_t b0, uint32_t b1) {
    asm volatile("mma.sync.aligned.m16n8k8.row.col.f32.tf32.tf32.f32 "
                 "{%0,%1,%2,%3}, {%4,%5,%6,%7}, {%8,%9}, {%0,%1,%2,%3};"
                 : "+f"(d[0]), "+f"(d[1]), "+f"(d[2]), "+f"(d[3])
                 : "r"(a0), "r"(a1), "r"(a2), "r"(a3), "r"(b0), "r"(b1));
}

__device__ __forceinline__ void zero_acc(float (&acc)[4][4][4]) {
#pragma unroll
    for (int i = 0; i < 4; ++i)
#pragma unroll
        for (int j = 0; j < 4; ++j)
#pragma unroll
            for (int q = 0; q < 4; ++q) acc[i][j][q] = 0.0f;
}

// 128x128x128 GEMM, 8 warps, 64x32 warp tiles, atom-packed operands.
// aA/aB: per-lane byte addresses (base + tilebase + lane terms).
// tile stride (16 rows) = 256B; k-step stride = 4096B.
// PREF: stage W[l+1]^T (global row-major [c][u]) into F_WT.
template<bool PREF>
__device__ __forceinline__ void gemm128(uint32_t aA, uint32_t aB,
                                        float (&acc)[4][4][4],
                                        const float* __restrict__ wg,
                                        float* __restrict__ smf,
                                        int warp, int lane) {
    float4 ring[4];
    int cbase = 0, ubase = 0, wbase = 0;
    if (PREF) {
        cbase = lane & 7;                       // c = 8*kk + cbase
        ubase = warp * 16 + ((lane >> 3) << 2); // 4 consecutive u per lane
        wbase = F_WT + (cbase >> 2) * 512 + (ubase >> 3) * 32 + (cbase & 3);
#pragma unroll
        for (int r = 0; r < 4; ++r)
            ring[r] = *(const float4*)(wg + (8 * r + cbase) * 128 + ubase);
    }
    uint32_t A[2][4][4];
    uint32_t B[2][2][4];
    // k = 0 fragments
#pragma unroll
    for (int mt = 0; mt < 4; ++mt)
        ldsm4(aA + mt * 256u, A[0][mt][0], A[0][mt][1], A[0][mt][2], A[0][mt][3]);
#pragma unroll
    for (int nb = 0; nb < 2; ++nb)
        ldsm4(aB + nb * 256u, B[0][nb][0], B[0][nb][1], B[0][nb][2], B[0][nb][3]);

#pragma unroll
    for (int k = 0; k < 16; ++k) {
        const int cur = k & 1, nxt = cur ^ 1;
        if (k < 15) {
#pragma unroll
            for (int mt = 0; mt < 4; ++mt)
                ldsm4(aA + mt * 256u + (uint32_t)(k + 1) * 4096u,
                      A[nxt][mt][0], A[nxt][mt][1], A[nxt][mt][2], A[nxt][mt][3]);
#pragma unroll
            for (int nb = 0; nb < 2; ++nb)
                ldsm4(aB + nb * 256u + (uint32_t)(k + 1) * 4096u,
                      B[nxt][nb][0], B[nxt][nb][1], B[nxt][nb][2], B[nxt][nb][3]);
        }
#pragma unroll
        for (int mt = 0; mt < 4; ++mt)
#pragma unroll
            for (int nt = 0; nt < 4; ++nt)
                mma8(acc[mt][nt],
                     A[cur][mt][0], A[cur][mt][1], A[cur][mt][2], A[cur][mt][3],
                     B[cur][nt >> 1][nt & 1], B[cur][nt >> 1][(nt & 1) + 2]);
        if (PREF && k >= 1) {
            const int kk = k - 1;
            float4 v = ring[kk & 3];
            int w = wbase + kk * 1024;
            int us = (ubase & 7) * 4;
            smf[w + us +  0] = tf32r(v.x);
            smf[w + us +  4] = tf32r(v.y);
            smf[w + us +  8] = tf32r(v.z);
            smf[w + us + 12] = tf32r(v.w);
            if (kk + 4 < 16)
                ring[kk & 3] = *(const float4*)(wg + (8 * (kk + 4) + cbase) * 128 + ubase);
        }
    }
    if (PREF) {
        float4 v = ring[15 & 3];
        int w = wbase + 15 * 1024;
        int us = (ubase & 7) * 4;
        smf[w + us +  0] = tf32r(v.x);
        smf[w + us +  4] = tf32r(v.y);
        smf[w + us +  8] = tf32r(v.z);
        smf[w + us + 12] = tf32r(v.w);
    }
}

__global__ __launch_bounds__(NTH, 1)
void gcn_mma_kernel(const int* __restrict__ pdg,
                    const float* __restrict__ feat,
                    const float* __restrict__ adj,
                    const float* __restrict__ mask,
                    const float* __restrict__ emb,
                    const float* __restrict__ W_in,
                    const float* __restrict__ b_in,
                    const float* __restrict__ W_h,
                    const float* __restrict__ b_h,
                    const float* __restrict__ W_out,
                    const float* __restrict__ b_out,
                    float* __restrict__ out)
{
    extern __shared__ float smf[];
    const uint32_t SB = smem_u32(smf);

    const int b    = blockIdx.x;
    const int tid  = threadIdx.x;
    const int lane = tid & 31;
    const int warp = tid >> 5;          // 0..7

    // 8 warps: 2 (m) x 4 (n), warp tile 64x32
    const int m0 = (warp >> 2) * 64;
    const int n0 = (warp & 3) * 32;

    // per-lane fragment byte offset within a (tile, k-step) block
    const uint32_t laneFrag = (uint32_t)((lane >> 4) * 2048
                                       + ((lane >> 3) & 1) * 128
                                       + (lane & 7) * 16);

    // epilogue pattern
    const int er = lane >> 2;           // 0..7 (= row&7)
    const int ec = (lane & 3) * 2;      // 0,2,4,6

    const float* adjb = adj + (size_t)b * 16384;

    // ================= staging =================
    // adj -> ADJ (cvt): warp covers 8 rows x 4 k-blocks per iter
#pragma unroll
    for (int ii = 0; ii < 16; ++ii) {
        int row = (ii >> 3) * 64 + warp * 8 + (lane >> 2);
        int c4  = (ii & 7) * 4 + (lane & 3);
        float4 v = *(const float4*)(adjb + row * 128 + c4 * 4);
        float4 w = make_float4(tf32r(v.x), tf32r(v.y), tf32r(v.z), tf32r(v.w));
        *(float4*)&smf[F_ADJ + c4 * 512 + (row >> 3) * 32 + (row & 7) * 4] = w;
    }
    {   // W_h[0]^T -> WT (cvt), PREF-identical mapping
        int cbase = lane & 7;
        int ubase = warp * 16 + ((lane >> 3) << 2);
        int wbase = F_WT + (cbase >> 2) * 512 + (ubase >> 3) * 32 + (cbase & 3);
        int us = (ubase & 7) * 4;
#pragma unroll
        for (int kk = 0; kk < 16; ++kk) {
            float4 v = *(const float4*)(W_h + (8 * kk + cbase) * 128 + ubase);
            int w = wbase + kk * 1024;
            smf[w + us +  0] = tf32r(v.x);
            smf[w + us +  4] = tf32r(v.y);
            smf[w + us +  8] = tf32r(v.z);
            smf[w + us + 12] = tf32r(v.w);
        }
    }
    if (tid < 128) {                    // x0 -> X0 (cvt), rows=p, k=c(16)
        int p = tid;
        float4 f0 = *(const float4*)(feat + ((size_t)b * 128 + p) * 8);
        float4 f1 = *(const float4*)(feat + ((size_t)b * 128 + p) * 8 + 4);
        int pg = pdg[(size_t)b * 128 + p];
        float4 e0 = *(const float4*)(emb + pg * 8);
        float4 e1 = *(const float4*)(emb + pg * 8 + 4);
        float vv[16] = {f0.x,f0.y,f0.z,f0.w, f1.x,f1.y,f1.z,f1.w,
                        e0.x,e0.y,e0.z,e0.w, e1.x,e1.y,e1.z,e1.w};
        int base = F_X0 + (p >> 3) * 32 + (p & 7) * 4;
#pragma unroll
        for (int jb = 0; jb < 4; ++jb)
            *(float4*)&smf[base + jb * 512] =
                make_float4(tf32r(vv[4*jb]), tf32r(vv[4*jb+1]),
                            tf32r(vv[4*jb+2]), tf32r(vv[4*jb+3]));
    }
#pragma unroll
    for (int i = 0; i < 2; ++i) {       // W_in^T -> WINT (cvt), rows=u, k=c(16)
        int idx = i * 256 + tid;
        int c = idx >> 5, u0 = (idx & 31) * 4;
        float4 wv = *(const float4*)(W_in + idx * 4);
        int base = F_WINT + (c >> 2) * 512 + (u0 >> 3) * 32 + (c & 3);
        int us = (u0 & 7) * 4;
        smf[base + us +  0] = tf32r(wv.x);
        smf[base + us +  4] = tf32r(wv.y);
        smf[base + us +  8] = tf32r(wv.z);
        smf[base + us + 12] = tf32r(wv.w);
    }
    if (tid < 192) {                    // b_h
        *(float4*)&smf[F_BIA + tid * 4] = *(const float4*)(b_h + tid * 4);
    }
    if (tid < 32) {                     // b_in
        *(float4*)&smf[F_BIN + tid * 4] = *(const float4*)(b_in + tid * 4);
    } else if (tid < 64) {              // mask
        int q = tid - 32;
        *(float4*)&smf[F_MSK + q * 4] = *(const float4*)(mask + (size_t)b * 128 + q * 4);
    } else if (tid < 96) {              // W_out
        int q = tid - 64;
        *(float4*)&smf[F_WO + q * 4] = *(const float4*)(W_out + q * 4);
    } else if (tid == 96) {
        smf[F_BOUT] = b_out[0];
    }
    __syncthreads();

    if (warp == 0) {                    // denom
        float s = smf[F_MSK + lane] + smf[F_MSK + lane + 32]
                + smf[F_MSK + lane + 64] + smf[F_MSK + lane + 96];
#pragma unroll
        for (int o = 16; o; o >>= 1) s += __shfl_down_sync(0xffffffffu, s, o);
        if (lane == 0) smf[F_RED + 7] = fmaxf(s, 1.0f);
    }

    float acc[4][4][4];

    // ================= input GEMM: X = x0 @ W_in + b_in (K=16) =================
    zero_acc(acc);
    {
        uint32_t aA = SB + F_X0 * 4   + (uint32_t)(m0 * 16) + laneFrag;
        uint32_t aB = SB + F_WINT * 4 + (uint32_t)(n0 * 16) + laneFrag;
#pragma unroll
        for (int k = 0; k < 2; ++k) {
            uint32_t A4[4][4], B4[2][4];
#pragma unroll
            for (int mt = 0; mt < 4; ++mt)
                ldsm4(aA + mt * 256u + k * 4096u,
                      A4[mt][0], A4[mt][1], A4[mt][2], A4[mt][3]);
#pragma unroll
            for (int nb = 0; nb < 2; ++nb)
                ldsm4(aB + nb * 256u + k * 4096u,
                      B4[nb][0], B4[nb][1], B4[nb][2], B4[nb][3]);
#pragma unroll
            for (int mt = 0; mt < 4; ++mt)
#pragma unroll
                for (int nt = 0; nt < 4; ++nt)
                    mma8(acc[mt][nt], A4[mt][0], A4[mt][1], A4[mt][2], A4[mt][3],
                         B4[nt >> 1][nt & 1], B4[nt >> 1][(nt & 1) + 2]);
        }
    }
    // epilogue: + b_in, cvt, store X (rows=p, k=u) into ACT
#pragma unroll
    for (int mt = 0; mt < 4; ++mt)
#pragma unroll
        for (int nt = 0; nt < 4; ++nt) {
            int u0 = n0 + nt * 8 + ec;
            int w  = F_ACT + ((u0 >> 2) * 512) + ((m0 >> 3) + 2 * mt) * 32
                   + er * 4 + (u0 & 3);
            float bi0 = smf[F_BIN + u0], bi1 = smf[F_BIN + u0 + 1];
            *(float2*)&smf[w] =
                make_float2(tf32r(acc[mt][nt][0] + bi0), tf32r(acc[mt][nt][1] + bi1));
            *(float2*)&smf[w + 32] =
                make_float2(tf32r(acc[mt][nt][2] + bi0), tf32r(acc[mt][nt][3] + bi1));
        }
    __syncthreads();

    // ================= hidden layers =================
#pragma unroll 1
    for (int l = 0; l < NHID; ++l) {
        // GEMM1 (flipped): Y^T[u][p] : A = WT (rows u), B^T = X (rows p, k=u)
        zero_acc(acc);
        gemm128<false>(SB + F_WT * 4  + (uint32_t)(m0 * 16) + laneFrag,
                       SB + F_ACT * 4 + (uint32_t)(n0 * 16) + laneFrag,
                       acc, nullptr, smf, warp, lane);
        __syncthreads();
        // epi1: relu(+bias over u), cvt, store Y^T (rows=u, k=p) into ACT
#pragma unroll
        for (int mt = 0; mt < 4; ++mt) {
            int u0 = m0 + mt * 16 + er;
            float bi  = smf[F_BIA + l * 128 + u0];
            float bi8 = smf[F_BIA + l * 128 + u0 + 8];
#pragma unroll
            for (int nt = 0; nt < 4; ++nt) {
                int p0 = n0 + nt * 8 + ec;
                int w  = F_ACT + ((p0 >> 2) * 512) + (u0 >> 3) * 32
                       + (u0 & 7) * 4 + (p0 & 3);
                *(float2*)&smf[w] =
                    make_float2(tf32r(fmaxf(acc[mt][nt][0] + bi, 0.0f)),
                                tf32r(fmaxf(acc[mt][nt][1] + bi, 0.0f)));
                // u0+8: same row-group (u0&7 < 8 -> +8 crosses into next group)
                int w8 = F_ACT + ((p0 >> 2) * 512) + ((u0 + 8) >> 3) * 32
                       + ((u0 + 8) & 7) * 4 + (p0 & 3);
                *(float2*)&smf[w8] =
                    make_float2(tf32r(fmaxf(acc[mt][nt][2] + bi8, 0.0f)),
                                tf32r(fmaxf(acc[mt][nt][3] + bi8, 0.0f)));
            }
        }
        __syncthreads();

        // GEMM2: X'[p][u] : A = ADJ (rows p), B^T = Y^T (rows u, k=p)
        zero_acc(acc);
        if (l + 1 < NHID)
            gemm128<true>(SB + F_ADJ * 4 + (uint32_t)(m0 * 16) + laneFrag,
                          SB + F_ACT * 4 + (uint32_t)(n0 * 16) + laneFrag,
                          acc, W_h + (size_t)(l + 1) * 16384, smf, warp, lane);
        else
            gemm128<false>(SB + F_ADJ * 4 + (uint32_t)(m0 * 16) + laneFrag,
                           SB + F_ACT * 4 + (uint32_t)(n0 * 16) + laneFrag,
                           acc, nullptr, smf, warp, lane);
        __syncthreads();
        // epi2: store X' (rows=p, k=u) into ACT (cvt unless last layer)
        const bool last = (l == NHID - 1);
#pragma unroll
        for (int mt = 0; mt < 4; ++mt)
#pragma unroll
            for (int nt = 0; nt < 4; ++nt) {
                int u0 = n0 + nt * 8 + ec;
                int w  = F_ACT + ((u0 >> 2) * 512) + ((m0 >> 3) + 2 * mt) * 32
                       + er * 4 + (u0 & 3);
                float v0 = acc[mt][nt][0], v1 = acc[mt][nt][1];
                float v2 = acc[mt][nt][2], v3 = acc[mt][nt][3];
                if (!last) { v0 = tf32r(v0); v1 = tf32r(v1); v2 = tf32r(v2); v3 = tf32r(v3); }
                *(float2*)&smf[w]      = make_float2(v0, v1);
                *(float2*)&smf[w + 32] = make_float2(v2, v3);
            }
        __syncthreads();
    }

    // ================= masked mean pool + output projection =================
    {
        int u = tid & 127;
        int h = tid >> 7;                      // 0..1
        int ub = F_ACT + (u >> 2) * 512 + (u & 3);
        float s = 0.0f;
#pragma unroll 8
        for (int i = 0; i < 64; ++i) {
            int p = h * 64 + i;
            s += smf[ub + (p >> 3) * 32 + (p & 7) * 4] * smf[F_MSK + p];
        }
        smf[F_PART + h * 128 + u] = s;
    }
    __syncthreads();
    if (tid < 128) {
        float pooled = (smf[F_PART + tid] + smf[F_PART + 128 + tid]) / smf[F_RED + 7];
        float v = pooled * smf[F_WO + tid];
#pragma unroll
        for (int o = 16; o; o >>= 1) v += __shfl_down_sync(0xffffffffu, v, o);
        if ((tid & 31) == 0) smf[F_RED + (tid >> 5)] = v;
    }
    __syncthreads();
    if (tid == 0)
        out[b] = smf[F_RED + 0] + smf[F_RED + 1] + smf[F_RED + 2] + smf[F_RED + 3]
               + smf[F_BOUT];
}

extern "C" void kernel_launch(void* const* d_in, const int* in_sizes, int n_in,
                              void* d_out, int out_size)
{
    const int*   pdg   = (const int*)  d_in[0];
    const float* feat  = (const float*)d_in[1];
    const float* adjp  = (const float*)d_in[2];
    const float* maskp = (const float*)d_in[3];
    const float* emb   = (const float*)d_in[4];
    const float* W_in  = (const float*)d_in[5];
    const float* b_in  = (const float*)d_in[6];
    const float* W_h   = (const float*)d_in[7];
    const float* b_h   = (const float*)d_in[8];
    const float* W_out = (const float*)d_in[9];
    const float* b_out = (const float*)d_in[10];
    float* out = (float*)d_out;

    const int B = in_sizes[0] / 128;

    cudaFuncSetAttribute(gcn_mma_kernel,
                         cudaFuncAttributeMaxDynamicSharedMemorySize, SMEM_BYTES);
    gcn_mma_kernel<<<B, NTH, SMEM_BYTES>>>(
        pdg, feat, adjp, maskp, emb, W_in, b_in, W_h, b_h, W_out, b_out, out);
}

// round 12
// speedup vs baseline: 1.0682x; 1.0682x over previous
#include <cuda_runtime.h>
#include <cstdint>

#define RL   132
#define NTH  256
#define NHID 6

// float offsets in dynamic smem
#define F_ADJ  0                 // 128*132 adj row-major (A of GEMM2)
#define F_ACT  16896             // 128*132 X / Y^T / X' multiplexed
#define F_WT   33792             // 128*132 W^T[u][c] (A of GEMM1)
#define F_X0   50688             // 128*16 input features (A of input GEMM)
#define F_WINT 52736             // 128*24 W_in^T (B of input GEMM)
#define F_BIN  55808             // 128
#define F_BIA  55936             // 768
#define F_MSK  56704             // 128
#define F_WO   56832             // 128
#define F_PART 56960             // 256
#define F_RED  57472             // 8 (RED[7] = denom)
#define F_BOUT 57480
#define SMEM_FLOATS 57488
#define SMEM_BYTES  (SMEM_FLOATS * 4)

__device__ __forceinline__ uint32_t smem_u32(const void* p) {
    uint32_t a;
    asm("{ .reg .u64 t; cvta.to.shared.u64 t, %1; cvt.u32.u64 %0, t; }" : "=r"(a) : "l"(p));
    return a;
}

__device__ __forceinline__ float tf32r(float x) {
    float y;
    asm("cvt.rna.tf32.f32 %0, %1;" : "=f"(y) : "f"(x));
    return y;
}

__device__ __forceinline__ void ldsm4(uint32_t addr, uint32_t& r0, uint32_t& r1,
                                      uint32_t& r2, uint32_t& r3) {
    asm volatile("ldmatrix.sync.aligned.m8n8.x4.shared.b16 {%0,%1,%2,%3}, [%4];"
                 : "=r"(r0), "=r"(r1), "=r"(r2), "=r"(r3) : "r"(addr));
}

__device__ __forceinline__ void mma8(float* d,
                                     uint32_t a0, uint32_t a1, uint32_t a2, uint32_t a3,
                                     uint32_t b0, uint32_t b1) {
    asm volatile("mma.sync.aligned.m16n8k8.row.col.f32.tf32.tf32.f32 "
                 "{%0,%1,%2,%3}, {%4,%5,%6,%7}, {%8,%9}, {%0,%1,%2,%3};"
                 : "+f"(d[0]), "+f"(d[1]), "+f"(d[2]), "+f"(d[3])
                 : "r"(a0), "r"(a1), "r"(a2), "r"(a3), "r"(b0), "r"(b1));
}

__device__ __forceinline__ void zero_acc(float (&acc)[4][4][4]) {
#pragma unroll
    for (int i = 0; i < 4; ++i)
#pragma unroll
        for (int j = 0; j < 4; ++j)
#pragma unroll
            for (int q = 0; q < 4; ++q) acc[i][j][q] = 0.0f;
}

// 128x128x128 GEMM, 8 warps, 64x32 warp tiles, RL-132 row-major operands.
// DEPTH-3 k-pipeline: iteration k prefetches fragments for k+2 (slot (k+2)%3),
// then runs the 16 mmas on slot k%3 (loaded two iterations ago -> no stall).
// PREF: stage W[l+1]^T (global row-major [c][u]) into F_WT under the MMA window.
template<bool PREF>
__device__ __forceinline__ void gemm128(uint32_t aA, uint32_t aB,
                                        float (&acc)[4][4][4],
                                        const float* __restrict__ wg,
                                        float* __restrict__ smf,
                                        int warp, int lane) {
    const uint32_t MSTEP = 16u * RL * 4u;
    uint32_t A[3][4][4];
    uint32_t B[3][2][4];
    float4 ring[4];
    int cbase = 0, ubase = 0;
    if (PREF) {
        cbase = lane & 7;                       // c = 8k + cbase
        ubase = warp * 16 + ((lane >> 3) << 2); // 4 consecutive u per lane
#pragma unroll
        for (int r = 0; r < 4; ++r)
            ring[r] = *(const float4*)(wg + (8 * r + cbase) * 128 + ubase);
    }
    // prologue: load k=0 -> slot 0, k=1 -> slot 1
#pragma unroll
    for (int k = 0; k < 2; ++k) {
#pragma unroll
        for (int mt = 0; mt < 4; ++mt)
            ldsm4(aA + mt * MSTEP + (uint32_t)k * 32u,
                  A[k][mt][0], A[k][mt][1], A[k][mt][2], A[k][mt][3]);
#pragma unroll
        for (int nb = 0; nb < 2; ++nb)
            ldsm4(aB + nb * MSTEP + (uint32_t)k * 32u,
                  B[k][nb][0], B[k][nb][1], B[k][nb][2], B[k][nb][3]);
    }

#pragma unroll
    for (int k = 0; k < 16; ++k) {
        const int cs = k % 3;
        const int ps = (k + 2) % 3;
        // prefetch k+2 first: no consumer for a full iteration
        if (k < 14) {
#pragma unroll
            for (int mt = 0; mt < 4; ++mt)
                ldsm4(aA + mt * MSTEP + (uint32_t)(k + 2) * 32u,
                      A[ps][mt][0], A[ps][mt][1], A[ps][mt][2], A[ps][mt][3]);
#pragma unroll
            for (int nb = 0; nb < 2; ++nb)
                ldsm4(aB + nb * MSTEP + (uint32_t)(k + 2) * 32u,
                      B[ps][nb][0], B[ps][nb][1], B[ps][nb][2], B[ps][nb][3]);
        }
        // mma burst on slot cs (ready since iteration k-2)
#pragma unroll
        for (int mt = 0; mt < 4; ++mt)
#pragma unroll
            for (int nt = 0; nt < 4; ++nt)
                mma8(acc[mt][nt],
                     A[cs][mt][0], A[cs][mt][1], A[cs][mt][2], A[cs][mt][3],
                     B[cs][nt >> 1][nt & 1], B[cs][nt >> 1][(nt & 1) + 2]);
        if (PREF && k >= 1) {
            const int kk = k - 1;
            const int c = 8 * kk + cbase;
            float4 v = ring[kk & 3];
            smf[F_WT + (ubase + 0) * RL + c] = tf32r(v.x);
            smf[F_WT + (ubase + 1) * RL + c] = tf32r(v.y);
            smf[F_WT + (ubase + 2) * RL + c] = tf32r(v.z);
            smf[F_WT + (ubase + 3) * RL + c] = tf32r(v.w);
            if (kk + 4 < 16)
                ring[kk & 3] = *(const float4*)(wg + (8 * (kk + 4) + cbase) * 128 + ubase);
        }
    }
    if (PREF) {
        const int c = 8 * 15 + cbase;
        float4 v = ring[15 & 3];
        smf[F_WT + (ubase + 0) * RL + c] = tf32r(v.x);
        smf[F_WT + (ubase + 1) * RL + c] = tf32r(v.y);
        smf[F_WT + (ubase + 2) * RL + c] = tf32r(v.z);
        smf[F_WT + (ubase + 3) * RL + c] = tf32r(v.w);
    }
}

__global__ __launch_bounds__(NTH, 1)
void gcn_mma_kernel(const int* __restrict__ pdg,
                    const float* __restrict__ feat,
                    const float* __restrict__ adj,
                    const float* __restrict__ mask,
                    const float* __restrict__ emb,
                    const float* __restrict__ W_in,
                    const float* __restrict__ b_in,
                    const float* __restrict__ W_h,
                    const float* __restrict__ b_h,
                    const float* __restrict__ W_out,
                    const float* __restrict__ b_out,
                    float* __restrict__ out)
{
    extern __shared__ float smf[];
    const uint32_t SB = smem_u32(smf);

    const int b    = blockIdx.x;
    const int tid  = threadIdx.x;
    const int lane = tid & 31;
    const int warp = tid >> 5;          // 0..7

    // 8 warps: 2 (m) x 4 (n), warp tile 64x32
    const int m0 = (warp >> 2) * 64;
    const int n0 = (warp & 3) * 32;

    // ldmatrix per-thread segment pattern
    const int aRow   = (lane & 7) + ((lane >> 3) & 1) * 8;
    const int aCol16 = lane >> 4;
    const uint32_t fragOff = (uint32_t)(aRow * RL) * 4 + (uint32_t)aCol16 * 16;

    // epilogue pattern
    const int er = lane >> 2;
    const int ec = (lane & 3) * 2;

    const float* adjb = adj + (size_t)b * 16384;

    // ================= staging =================
#pragma unroll
    for (int i = 0; i < 16; ++i) {             // adj -> ADJ (cvt), direct
        int idx = i * 256 + tid;
        int row = idx >> 5, c4 = idx & 31;
        float4 v = *(const float4*)(adjb + row * 128 + c4 * 4);
        float4 w = make_float4(tf32r(v.x), tf32r(v.y), tf32r(v.z), tf32r(v.w));
        *(float4*)&smf[F_ADJ + row * RL + c4 * 4] = w;
    }
    {                                          // W_h[0]^T -> WT (cvt), PREF-identical map
        int cb = lane & 7;
        int u0 = warp * 16 + ((lane >> 3) << 2);
#pragma unroll
        for (int kk = 0; kk < 16; ++kk) {
            int c = 8 * kk + cb;
            float4 v = *(const float4*)(W_h + c * 128 + u0);
            smf[F_WT + (u0 + 0) * RL + c] = tf32r(v.x);
            smf[F_WT + (u0 + 1) * RL + c] = tf32r(v.y);
            smf[F_WT + (u0 + 2) * RL + c] = tf32r(v.z);
            smf[F_WT + (u0 + 3) * RL + c] = tf32r(v.w);
        }
    }
    if (tid < 128) {                           // x0 -> X0 (cvt)
        int p = tid;
        float4 f0 = *(const float4*)(feat + ((size_t)b * 128 + p) * 8);
        float4 f1 = *(const float4*)(feat + ((size_t)b * 128 + p) * 8 + 4);
        int pg = pdg[(size_t)b * 128 + p];
        float4 e0 = *(const float4*)(emb + pg * 8);
        float4 e1 = *(const float4*)(emb + pg * 8 + 4);
        float vv[16] = {f0.x,f0.y,f0.z,f0.w, f1.x,f1.y,f1.z,f1.w,
                        e0.x,e0.y,e0.z,e0.w, e1.x,e1.y,e1.z,e1.w};
#pragma unroll
        for (int j = 0; j < 16; ++j) smf[F_X0 + p * 16 + j] = tf32r(vv[j]);
    }
#pragma unroll
    for (int i = 0; i < 2; ++i) {              // W_in^T -> WINT (cvt)
        int idx = i * 256 + tid;
        int c = idx >> 5, u0 = (idx & 31) * 4;
        float4 wv = *(const float4*)(W_in + idx * 4);
        smf[F_WINT + (u0 + 0) * 24 + c] = tf32r(wv.x);
        smf[F_WINT + (u0 + 1) * 24 + c] = tf32r(wv.y);
        smf[F_WINT + (u0 + 2) * 24 + c] = tf32r(wv.z);
        smf[F_WINT + (u0 + 3) * 24 + c] = tf32r(wv.w);
    }
    if (tid < 192) {                           // b_h
        *(float4*)&smf[F_BIA + tid * 4] = *(const float4*)(b_h + tid * 4);
    }
    if (tid < 32) {                            // b_in
        *(float4*)&smf[F_BIN + tid * 4] = *(const float4*)(b_in + tid * 4);
    } else if (tid < 64) {                     // mask
        int q = tid - 32;
        *(float4*)&smf[F_MSK + q * 4] = *(const float4*)(mask + (size_t)b * 128 + q * 4);
    } else if (tid < 96) {                     // W_out
        int q = tid - 64;
        *(float4*)&smf[F_WO + q * 4] = *(const float4*)(W_out + q * 4);
    } else if (tid == 96) {
        smf[F_BOUT] = b_out[0];
    }
    __syncthreads();

    if (warp == 0) {                           // denom
        float s = smf[F_MSK + lane] + smf[F_MSK + lane + 32]
                + smf[F_MSK + lane + 64] + smf[F_MSK + lane + 96];
#pragma unroll
        for (int o = 16; o; o >>= 1) s += __shfl_down_sync(0xffffffffu, s, o);
        if (lane == 0) smf[F_RED + 7] = fmaxf(s, 1.0f);
    }

    float acc[4][4][4];

    // ================= input GEMM: X = x0 @ W_in + b_in (K=16) =================
    zero_acc(acc);
    {
        uint32_t aA = SB + F_X0 * 4
                    + (uint32_t)((m0 + aRow) * 16) * 4 + (uint32_t)aCol16 * 16;
        uint32_t aB = SB + F_WINT * 4
                    + (uint32_t)((n0 + aRow) * 24) * 4 + (uint32_t)aCol16 * 16;
        const uint32_t MSA = 16u * 16u * 4u;
        const uint32_t MSB = 16u * 24u * 4u;
#pragma unroll
        for (int k = 0; k < 2; ++k) {
            uint32_t A4[4][4], B4[2][4];
#pragma unroll
            for (int mt = 0; mt < 4; ++mt)
                ldsm4(aA + mt * MSA + k * 32u, A4[mt][0], A4[mt][1], A4[mt][2], A4[mt][3]);
#pragma unroll
            for (int nb = 0; nb < 2; ++nb)
                ldsm4(aB + nb * MSB + k * 32u, B4[nb][0], B4[nb][1], B4[nb][2], B4[nb][3]);
#pragma unroll
            for (int mt = 0; mt < 4; ++mt)
#pragma unroll
                for (int nt = 0; nt < 4; ++nt)
                    mma8(acc[mt][nt], A4[mt][0], A4[mt][1], A4[mt][2], A4[mt][3],
                         B4[nt >> 1][nt & 1], B4[nt >> 1][(nt & 1) + 2]);
        }
    }
    // epilogue: + b_in, cvt, store X row-major into ACT
#pragma unroll
    for (int mt = 0; mt < 4; ++mt)
#pragma unroll
        for (int nt = 0; nt < 4; ++nt) {
            int p0 = m0 + mt * 16 + er;
            int u0 = n0 + nt * 8 + ec;
            float bi0 = smf[F_BIN + u0], bi1 = smf[F_BIN + u0 + 1];
            *(float2*)&smf[F_ACT + p0 * RL + u0] =
                make_float2(tf32r(acc[mt][nt][0] + bi0), tf32r(acc[mt][nt][1] + bi1));
            *(float2*)&smf[F_ACT + (p0 + 8) * RL + u0] =
                make_float2(tf32r(acc[mt][nt][2] + bi0), tf32r(acc[mt][nt][3] + bi1));
        }
    __syncthreads();

    // ================= hidden layers =================
    const uint32_t actB = SB + F_ACT * 4;
    const uint32_t adjB = SB + F_ADJ * 4;
    const uint32_t wtB  = SB + F_WT * 4;

#pragma unroll 1
    for (int l = 0; l < NHID; ++l) {
        // GEMM1 (flipped): Y^T[u][p] : A = WT (rows u), B^T = X (rows p)
        zero_acc(acc);
        gemm128<false>(wtB  + (uint32_t)(m0 * RL) * 4 + fragOff,
                       actB + (uint32_t)(n0 * RL) * 4 + fragOff,
                       acc, nullptr, smf, warp, lane);
        __syncthreads();
        // epi1: relu(+bias over u), cvt, store Y^T ROW-MAJOR (float2 along p)
#pragma unroll
        for (int mt = 0; mt < 4; ++mt) {
            int u0 = m0 + mt * 16 + er;
            float bi  = smf[F_BIA + l * 128 + u0];
            float bi8 = smf[F_BIA + l * 128 + u0 + 8];
#pragma unroll
            for (int nt = 0; nt < 4; ++nt) {
                int p0 = n0 + nt * 8 + ec;
                *(float2*)&smf[F_ACT + u0 * RL + p0] =
                    make_float2(tf32r(fmaxf(acc[mt][nt][0] + bi, 0.0f)),
                                tf32r(fmaxf(acc[mt][nt][1] + bi, 0.0f)));
                *(float2*)&smf[F_ACT + (u0 + 8) * RL + p0] =
                    make_float2(tf32r(fmaxf(acc[mt][nt][2] + bi8, 0.0f)),
                                tf32r(fmaxf(acc[mt][nt][3] + bi8, 0.0f)));
            }
        }
        __syncthreads();

        // GEMM2: X'[p][u] : A = ADJ (rows p), B^T = Y^T (rows u)
        zero_acc(acc);
        if (l + 1 < NHID)
            gemm128<true>(adjB + (uint32_t)(m0 * RL) * 4 + fragOff,
                          actB + (uint32_t)(n0 * RL) * 4 + fragOff,
                          acc, W_h + (size_t)(l + 1) * 16384, smf, warp, lane);
        else
            gemm128<false>(adjB + (uint32_t)(m0 * RL) * 4 + fragOff,
                           actB + (uint32_t)(n0 * RL) * 4 + fragOff,
                           acc, nullptr, smf, warp, lane);
        __syncthreads();
        // epi2: store X' row-major into ACT (cvt unless last layer)
        const bool last = (l == NHID - 1);
#pragma unroll
        for (int mt = 0; mt < 4; ++mt)
#pragma unroll
            for (int nt = 0; nt < 4; ++nt) {
                int p0 = m0 + mt * 16 + er;
                int u0 = n0 + nt * 8 + ec;
                float v0 = acc[mt][nt][0], v1 = acc[mt][nt][1];
                float v2 = acc[mt][nt][2], v3 = acc[mt][nt][3];
                if (!last) { v0 = tf32r(v0); v1 = tf32r(v1); v2 = tf32r(v2); v3 = tf32r(v3); }
                *(float2*)&smf[F_ACT + p0 * RL + u0]       = make_float2(v0, v1);
                *(float2*)&smf[F_ACT + (p0 + 8) * RL + u0] = make_float2(v2, v3);
            }
        __syncthreads();
    }

    // ================= masked mean pool + output projection =================
    {
        int u = tid & 127;
        int h = tid >> 7;                      // 0..1
        float s = 0.0f;
#pragma unroll 8
        for (int i = 0; i < 64; ++i) {
            int p = h * 64 + i;
            s += smf[F_ACT + p * RL + u] * smf[F_MSK + p];
        }
        smf[F_PART + h * 128 + u] = s;
    }
    __syncthreads();
    if (tid < 128) {
        float pooled = (smf[F_PART + tid] + smf[F_PART + 128 + tid]) / smf[F_RED + 7];
        float v = pooled * smf[F_WO + tid];
#pragma unroll
        for (int o = 16; o; o >>= 1) v += __shfl_down_sync(0xffffffffu, v, o);
        if ((tid & 31) == 0) smf[F_RED + (tid >> 5)] = v;
    }
    __syncthreads();
    if (tid == 0)
        out[b] = smf[F_RED + 0] + smf[F_RED + 1] + smf[F_RED + 2] + smf[F_RED + 3]
               + smf[F_BOUT];
}

extern "C" void kernel_launch(void* const* d_in, const int* in_sizes, int n_in,
                              void* d_out, int out_size)
{
    const int*   pdg   = (const int*)  d_in[0];
    const float* feat  = (const float*)d_in[1];
    const float* adjp  = (const float*)d_in[2];
    const float* maskp = (const float*)d_in[3];
    const float* emb   = (const float*)d_in[4];
    const float* W_in  = (const float*)d_in[5];
    const float* b_in  = (const float*)d_in[6];
    const float* W_h   = (const float*)d_in[7];
    const float* b_h   = (const float*)d_in[8];
    const float* W_out = (const float*)d_in[9];
    const float* b_out = (const float*)d_in[10];
    float* out = (float*)d_out;

    const int B = in_sizes[0] / 128;

    cudaFuncSetAttribute(gcn_mma_kernel,
                         cudaFuncAttributeMaxDynamicSharedMemorySize, SMEM_BYTES);
    gcn_mma_kernel<<<B, NTH, SMEM_BYTES>>>(
        pdg, feat, adjp, maskp, emb, W_in, b_in, W_h, b_h, W_out, b_out, out);
}

// round 13
// speedup vs baseline: 1.7737x; 1.6604x over previous
#include <cuda_runtime.h>
#include <cuda_fp16.h>
#include <cstdint>

#define NTH  256
#define NHID 6

// fp16 operands, 128x128, rows of 128 halves = 256B, XOR-swizzled:
//   byte(row, kh) = row*256 + (((kh>>3) ^ (row&7))<<4) + (kh&7)*2
// byte offsets:
#define B_ADJ   0
#define B_ACT   32768
#define B_WT    65536
#define B_X0    98304       // 128 rows x 32B (16 halves), unswizzled
#define B_WINT  102400      // 128 rows x 32B
// float-indexed misc (offsets in floats from smem base)
#define F_BIN   26624       // 128
#define F_BIA   26752       // 768 (pre-scaled by 8^-(l+1))
#define F_MSK   27520       // 128
#define F_WO    27648       // 128
#define F_PART  27776       // 256
#define F_RED   28032       // 8 (RED[7] = denom)
#define F_BOUT  28040
#define SMEM_BYTES 112192

__device__ __forceinline__ uint32_t smem_u32(const void* p) {
    uint32_t a;
    asm("{ .reg .u64 t; cvta.to.shared.u64 t, %1; cvt.u32.u64 %0, t; }" : "=r"(a) : "l"(p));
    return a;
}

__device__ __forceinline__ void ldsm4(uint32_t addr, uint32_t& r0, uint32_t& r1,
                                      uint32_t& r2, uint32_t& r3) {
    asm volatile("ldmatrix.sync.aligned.m8n8.x4.shared.b16 {%0,%1,%2,%3}, [%4];"
                 : "=r"(r0), "=r"(r1), "=r"(r2), "=r"(r3) : "r"(addr));
}

__device__ __forceinline__ void mma16(float* d,
                                      uint32_t a0, uint32_t a1, uint32_t a2, uint32_t a3,
                                      uint32_t b0, uint32_t b1) {
    asm volatile("mma.sync.aligned.m16n8k16.row.col.f32.f16.f16.f32 "
                 "{%0,%1,%2,%3}, {%4,%5,%6,%7}, {%8,%9}, {%0,%1,%2,%3};"
                 : "+f"(d[0]), "+f"(d[1]), "+f"(d[2]), "+f"(d[3])
                 : "r"(a0), "r"(a1), "r"(a2), "r"(a3), "r"(b0), "r"(b1));
}

__device__ __forceinline__ void zero_acc(float (&acc)[4][4][4]) {
#pragma unroll
    for (int i = 0; i < 4; ++i)
#pragma unroll
        for (int j = 0; j < 4; ++j)
#pragma unroll
            for (int q = 0; q < 4; ++q) acc[i][j][q] = 0.0f;
}

// swizzled half store
__device__ __forceinline__ void sth(char* smc, int buf, int row, int kh, __half v) {
    *(__half*)(smc + buf + row * 256 + ((((kh >> 3) ^ (row & 7))) << 4) + (kh & 7) * 2) = v;
}
__device__ __forceinline__ void sth2(char* smc, int buf, int row, int kh, __half2 v) {
    *(__half2*)(smc + buf + row * 256 + ((((kh >> 3) ^ (row & 7))) << 4) + (kh & 7) * 2) = v;
}

// 128x128x128 fp16 GEMM, 8 warps, 64x32 warp tiles, swizzled operands.
// tA[4], tB[2]: per-lane row-base byte addrs (buf + row*256). K = 8 steps of k16.
// PREF: stage W[l+1]^T (global row-major [c][u], fp32) into B_WT as fp16.
template<bool PREF>
__device__ __forceinline__ void gemm128(const uint32_t* tA, const uint32_t* tB,
                                        float (&acc)[4][4][4],
                                        const float* __restrict__ wg,
                                        char* smc, int warp, int lane,
                                        uint32_t csel, uint32_t rl) {
    float4 ring[4];
    int cbase = 0, ubase = 0;
    if (PREF) {
        cbase = lane & 7;
        ubase = warp * 16 + ((lane >> 3) << 2);
#pragma unroll
        for (int r = 0; r < 4; ++r)
            ring[r] = *(const float4*)(wg + (8 * r + cbase) * 128 + ubase);
    }
#pragma unroll
    for (int k = 0; k < 8; ++k) {
        const uint32_t cc = ((((uint32_t)k << 1) | csel) ^ rl) << 4;
        uint32_t A[4][4], B[2][4];
#pragma unroll
        for (int mt = 0; mt < 4; ++mt)
            ldsm4(tA[mt] + cc, A[mt][0], A[mt][1], A[mt][2], A[mt][3]);
#pragma unroll
        for (int nb = 0; nb < 2; ++nb)
            ldsm4(tB[nb] + cc, B[nb][0], B[nb][1], B[nb][2], B[nb][3]);
#pragma unroll
        for (int mt = 0; mt < 4; ++mt)
#pragma unroll
            for (int nt = 0; nt < 4; ++nt)
                mma16(acc[mt][nt], A[mt][0], A[mt][1], A[mt][2], A[mt][3],
                      B[nt >> 1][nt & 1], B[nt >> 1][(nt & 1) + 2]);
        if (PREF) {
#pragma unroll
            for (int h = 0; h < 2; ++h) {
                const int kk = 2 * k + h;
                const int c = 8 * kk + cbase;
                float4 v = ring[kk & 3];
                sth(smc, B_WT, ubase + 0, c, __float2half_rn(v.x));
                sth(smc, B_WT, ubase + 1, c, __float2half_rn(v.y));
                sth(smc, B_WT, ubase + 2, c, __float2half_rn(v.z));
                sth(smc, B_WT, ubase + 3, c, __float2half_rn(v.w));
                if (kk + 4 < 16)
                    ring[kk & 3] = *(const float4*)(wg + (8 * (kk + 4) + cbase) * 128 + ubase);
            }
        }
    }
}

__global__ __launch_bounds__(NTH, 2)
void gcn_mma_kernel(const int* __restrict__ pdg,
                    const float* __restrict__ feat,
                    const float* __restrict__ adj,
                    const float* __restrict__ mask,
                    const float* __restrict__ emb,
                    const float* __restrict__ W_in,
                    const float* __restrict__ b_in,
                    const float* __restrict__ W_h,
                    const float* __restrict__ b_h,
                    const float* __restrict__ W_out,
                    const float* __restrict__ b_out,
                    float* __restrict__ out)
{
    extern __shared__ float smf[];
    char* smc = (char*)smf;
    const uint32_t SB = smem_u32(smf);

    const int b    = blockIdx.x;
    const int tid  = threadIdx.x;
    const int lane = tid & 31;
    const int warp = tid >> 5;          // 0..7

    const int m0 = (warp >> 2) * 64;    // 2 (m) x 4 (n) warps, tile 64x32
    const int n0 = (warp & 3) * 32;

    const int aRow      = (lane & 7) + ((lane >> 3) & 1) * 8;  // 0..15
    const uint32_t csel = (uint32_t)(lane >> 4);               // 0..1
    const uint32_t rl   = (uint32_t)(aRow & 7);

    const int er = lane >> 2;           // 0..7
    const int ec = (lane & 3) * 2;      // 0,2,4,6

    const float* adjb = adj + (size_t)b * 16384;

    // ================= staging =================
#pragma unroll
    for (int i = 0; i < 16; ++i) {      // adj -> ADJ fp16 swizzled
        int idx = i * 256 + tid;
        int row = idx >> 5, c4 = idx & 31;
        float4 v = *(const float4*)(adjb + row * 128 + c4 * 4);
        sth2(smc, B_ADJ, row, c4 * 4,     __floats2half2_rn(v.x, v.y));
        sth2(smc, B_ADJ, row, c4 * 4 + 2, __floats2half2_rn(v.z, v.w));
    }
    {                                   // W_h[0]^T -> WT, PREF-identical map
        int cb = lane & 7;
        int u0 = warp * 16 + ((lane >> 3) << 2);
#pragma unroll
        for (int kk = 0; kk < 16; ++kk) {
            int c = 8 * kk + cb;
            float4 v = *(const float4*)(W_h + c * 128 + u0);
            sth(smc, B_WT, u0 + 0, c, __float2half_rn(v.x));
            sth(smc, B_WT, u0 + 1, c, __float2half_rn(v.y));
            sth(smc, B_WT, u0 + 2, c, __float2half_rn(v.z));
            sth(smc, B_WT, u0 + 3, c, __float2half_rn(v.w));
        }
    }
    if (tid < 128) {                    // x0 -> X0 (fp16, 32B rows, unswizzled)
        int p = tid;
        float4 f0 = *(const float4*)(feat + ((size_t)b * 128 + p) * 8);
        float4 f1 = *(const float4*)(feat + ((size_t)b * 128 + p) * 8 + 4);
        int pg = pdg[(size_t)b * 128 + p];
        float4 e0 = *(const float4*)(emb + pg * 8);
        float4 e1 = *(const float4*)(emb + pg * 8 + 4);
        __half2* d = (__half2*)(smc + B_X0 + p * 32);
        d[0] = __floats2half2_rn(f0.x, f0.y);
        d[1] = __floats2half2_rn(f0.z, f0.w);
        d[2] = __floats2half2_rn(f1.x, f1.y);
        d[3] = __floats2half2_rn(f1.z, f1.w);
        d[4] = __floats2half2_rn(e0.x, e0.y);
        d[5] = __floats2half2_rn(e0.z, e0.w);
        d[6] = __floats2half2_rn(e1.x, e1.y);
        d[7] = __floats2half2_rn(e1.z, e1.w);
    }
#pragma unroll
    for (int i = 0; i < 2; ++i) {       // W_in^T -> WINT (rows u, 16 halves)
        int idx = i * 256 + tid;
        int c = idx >> 5, u0 = (idx & 31) * 4;
        float4 wv = *(const float4*)(W_in + idx * 4);
        *(__half*)(smc + B_WINT + (u0 + 0) * 32 + c * 2) = __float2half_rn(wv.x);
        *(__half*)(smc + B_WINT + (u0 + 1) * 32 + c * 2) = __float2half_rn(wv.y);
        *(__half*)(smc + B_WINT + (u0 + 2) * 32 + c * 2) = __float2half_rn(wv.z);
        *(__half*)(smc + B_WINT + (u0 + 3) * 32 + c * 2) = __float2half_rn(wv.w);
    }
    if (tid < 192) {                    // b_h pre-scaled by 8^-(l+1)
        int l = tid >> 5;
        float s = exp2f(-3.0f * (float)(l + 1));
        float4 v = *(const float4*)(b_h + tid * 4);
        *(float4*)&smf[F_BIA + tid * 4] =
            make_float4(v.x * s, v.y * s, v.z * s, v.w * s);
    }
    if (tid < 32) {                     // b_in
        *(float4*)&smf[F_BIN + tid * 4] = *(const float4*)(b_in + tid * 4);
    } else if (tid < 64) {              // mask
        int q = tid - 32;
        *(float4*)&smf[F_MSK + q * 4] = *(const float4*)(mask + (size_t)b * 128 + q * 4);
    } else if (tid < 96) {              // W_out
        int q = tid - 64;
        *(float4*)&smf[F_WO + q * 4] = *(const float4*)(W_out + q * 4);
    } else if (tid == 96) {
        smf[F_BOUT] = b_out[0];
    }
    __syncthreads();

    if (warp == 0) {                    // denom
        float s = smf[F_MSK + lane] + smf[F_MSK + lane + 32]
                + smf[F_MSK + lane + 64] + smf[F_MSK + lane + 96];
#pragma unroll
        for (int o = 16; o; o >>= 1) s += __shfl_down_sync(0xffffffffu, s, o);
        if (lane == 0) smf[F_RED + 7] = fmaxf(s, 1.0f);
    }

    float acc[4][4][4];

    // per-lane tile row-base addresses for the three swizzled buffers
    uint32_t tACT[4], tADJ[4], tWT[4];
#pragma unroll
    for (int mt = 0; mt < 4; ++mt) {
        uint32_t rb = (uint32_t)(m0 + mt * 16 + aRow) * 256u;
        tADJ[mt] = SB + B_ADJ + rb;
        tACT[mt] = SB + B_ACT + rb;
        tWT[mt]  = SB + B_WT  + rb;
    }
    uint32_t nACT[2], nWT2[2];
#pragma unroll
    for (int nb = 0; nb < 2; ++nb) {
        uint32_t rb = (uint32_t)(n0 + nb * 16 + aRow) * 256u;
        nACT[nb] = SB + B_ACT + rb;
        nWT2[nb] = SB + B_WT  + rb;   // unused; placeholder symmetry
    }

    // ================= input GEMM: X = x0 @ W_in + b_in (K=16, 1 step) =========
    zero_acc(acc);
    {
        uint32_t A4[4][4], B4[2][4];
#pragma unroll
        for (int mt = 0; mt < 4; ++mt)
            ldsm4(SB + B_X0 + (uint32_t)(m0 + mt * 16 + aRow) * 32u + csel * 16u,
                  A4[mt][0], A4[mt][1], A4[mt][2], A4[mt][3]);
#pragma unroll
        for (int nb = 0; nb < 2; ++nb)
            ldsm4(SB + B_WINT + (uint32_t)(n0 + nb * 16 + aRow) * 32u + csel * 16u,
                  B4[nb][0], B4[nb][1], B4[nb][2], B4[nb][3]);
#pragma unroll
        for (int mt = 0; mt < 4; ++mt)
#pragma unroll
            for (int nt = 0; nt < 4; ++nt)
                mma16(acc[mt][nt], A4[mt][0], A4[mt][1], A4[mt][2], A4[mt][3],
                      B4[nt >> 1][nt & 1], B4[nt >> 1][(nt & 1) + 2]);
    }
    // epi: + b_in, store X fp16 (rows p, kh = u) into ACT
#pragma unroll
    for (int mt = 0; mt < 4; ++mt)
#pragma unroll
        for (int nt = 0; nt < 4; ++nt) {
            int p0 = m0 + mt * 16 + er;
            int u0 = n0 + nt * 8 + ec;
            float bi0 = smf[F_BIN + u0], bi1 = smf[F_BIN + u0 + 1];
            sth2(smc, B_ACT, p0,     u0, __floats2half2_rn(acc[mt][nt][0] + bi0,
                                                           acc[mt][nt][1] + bi1));
            sth2(smc, B_ACT, p0 + 8, u0, __floats2half2_rn(acc[mt][nt][2] + bi0,
                                                           acc[mt][nt][3] + bi1));
        }
    __syncthreads();

    // ================= hidden layers =================
#pragma unroll 1
    for (int l = 0; l < NHID; ++l) {
        // GEMM1 (flipped): Y^T[u][p] : A = WT (rows u), B^T = X (rows p, kh=u)
        zero_acc(acc);
        gemm128<false>(tWT, nACT, acc, nullptr, smc, warp, lane, csel, rl);
        __syncthreads();
        // epi1: Ytilde = relu(acc*0.125 + b*8^-(l+1)); store Y^T (rows u, kh=p)
#pragma unroll
        for (int mt = 0; mt < 4; ++mt) {
            int u0 = m0 + mt * 16 + er;
            float bi  = smf[F_BIA + l * 128 + u0];
            float bi8 = smf[F_BIA + l * 128 + u0 + 8];
#pragma unroll
            for (int nt = 0; nt < 4; ++nt) {
                int p0 = n0 + nt * 8 + ec;
                sth2(smc, B_ACT, u0, p0,
                     __floats2half2_rn(fmaxf(acc[mt][nt][0] * 0.125f + bi, 0.0f),
                                       fmaxf(acc[mt][nt][1] * 0.125f + bi, 0.0f)));
                sth2(smc, B_ACT, u0 + 8, p0,
                     __floats2half2_rn(fmaxf(acc[mt][nt][2] * 0.125f + bi8, 0.0f),
                                       fmaxf(acc[mt][nt][3] * 0.125f + bi8, 0.0f)));
            }
        }
        __syncthreads();

        // GEMM2: X'[p][u] : A = ADJ (rows p), B^T = Y^T (rows u, kh=p)
        zero_acc(acc);
        if (l + 1 < NHID)
            gemm128<true>(tADJ, nACT, acc, W_h + (size_t)(l + 1) * 16384,
                          smc, warp, lane, csel, rl);
        else
            gemm128<false>(tADJ, nACT, acc, nullptr, smc, warp, lane, csel, rl);
        __syncthreads();
        // epi2: store X' fp16 (rows p, kh = u) — already carries scale 8^-(l+1)
#pragma unroll
        for (int mt = 0; mt < 4; ++mt)
#pragma unroll
            for (int nt = 0; nt < 4; ++nt) {
                int p0 = m0 + mt * 16 + er;
                int u0 = n0 + nt * 8 + ec;
                sth2(smc, B_ACT, p0,     u0,
                     __floats2half2_rn(acc[mt][nt][0], acc[mt][nt][1]));
                sth2(smc, B_ACT, p0 + 8, u0,
                     __floats2half2_rn(acc[mt][nt][2], acc[mt][nt][3]));
            }
        __syncthreads();
    }

    // ================= masked mean pool + output projection =================
    {
        int u = tid & 127;
        int h = tid >> 7;                      // 0..1
        float s = 0.0f;
#pragma unroll 8
        for (int i = 0; i < 64; ++i) {
            int p = h * 64 + i;
            __half hv = *(const __half*)(smc + B_ACT + p * 256
                         + ((((u >> 3) ^ (p & 7))) << 4) + (u & 7) * 2);
            s += __half2float(hv) * smf[F_MSK + p];
        }
        smf[F_PART + h * 128 + u] = s;
    }
    __syncthreads();
    if (tid < 128) {
        // undo scale 8^-6 = 2^-18 exactly
        float pooled = (smf[F_PART + tid] + smf[F_PART + 128 + tid])
                       * 262144.0f / smf[F_RED + 7];
        float v = pooled * smf[F_WO + tid];
#pragma unroll
        for (int o = 16; o; o >>= 1) v += __shfl_down_sync(0xffffffffu, v, o);
        if ((tid & 31) == 0) smf[F_RED + (tid >> 5)] = v;
    }
    __syncthreads();
    if (tid == 0)
        out[b] = smf[F_RED + 0] + smf[F_RED + 1] + smf[F_RED + 2] + smf[F_RED + 3]
               + smf[F_BOUT];
}

extern "C" void kernel_launch(void* const* d_in, const int* in_sizes, int n_in,
                              void* d_out, int out_size)
{
    const int*   pdg   = (const int*)  d_in[0];
    const float* feat  = (const float*)d_in[1];
    const float* adjp  = (const float*)d_in[2];
    const float* maskp = (const float*)d_in[3];
    const float* emb   = (const float*)d_in[4];
    const float* W_in  = (const float*)d_in[5];
    const float* b_in  = (const float*)d_in[6];
    const float* W_h   = (const float*)d_in[7];
    const float* b_h   = (const float*)d_in[8];
    const float* W_out = (const float*)d_in[9];
    const float* b_out = (const float*)d_in[10];
    float* out = (float*)d_out;

    const int B = in_sizes[0] / 128;

    cudaFuncSetAttribute(gcn_mma_kernel,
                         cudaFuncAttributeMaxDynamicSharedMemorySize, SMEM_BYTES);
    gcn_mma_kernel<<<B, NTH, SMEM_BYTES>>>(
        pdg, feat, adjp, maskp, emb, W_in, b_in, W_h, b_h, W_out, b_out, out);
}